// round 13
// baseline (speedup 1.0000x reference)
#include <cuda_runtime.h>
#include <cstdint>

#define NROWS  512
#define INSIZE 512
#define KK     64
#define DD     16
#define MM     (KK * DD)        // 1024
#define OUTW   (INSIZE + KK)    // 576
#define BK     16
#define T      64
#define PART   (NROWS * MM)     // one split-K partial, K-major [k][row][d]

typedef unsigned long long ull;

__device__ float g_P[4 * PART];          // split-K partials (bias in z0)  8 MB
__device__ float g_part[NROWS * KK * 8]; // [k][i][slot]                   1 MB
__device__ int   g_cnt[16];              // per-kgroup arrival counters

// 36 tile-units: 8 diagonal + 28 upper-triangle
__constant__ int c_ua[36] = {0,1,2,3,4,5,6,7, 0,0,0,0,0,0,0, 1,1,1,1,1,1,
                             2,2,2,2,2, 3,3,3,3, 4,4,4, 5,5, 6};
__constant__ int c_ub[36] = {0,1,2,3,4,5,6,7, 1,2,3,4,5,6,7, 2,3,4,5,6,7,
                             3,4,5,6,7, 4,5,6,7, 5,6,7, 6,7, 7};

// ---------------------------------------------------------------------------
// helpers
// ---------------------------------------------------------------------------
__device__ __forceinline__ ull addf32x2(ull a, ull b) {
    ull r;
    asm("add.rn.f32x2 %0, %1, %2;" : "=l"(r) : "l"(a), "l"(b));
    return r;
}
__device__ __forceinline__ ull fmaf32x2(ull a, ull b, ull c) {
    ull r;
    asm("fma.rn.f32x2 %0, %1, %2, %3;" : "=l"(r) : "l"(a), "l"(b), "l"(c));
    return r;
}
__device__ __forceinline__ float lo32(ull v) {
    return __uint_as_float((unsigned int)v);
}
__device__ __forceinline__ float hi32(ull v) {
    return __uint_as_float((unsigned int)(v >> 32));
}
__device__ __forceinline__ float ex2f(float v) {
    float r;
    asm("ex2.approx.f32 %0, %1;" : "=f"(r) : "f"(v));
    return r;
}

#define NLOG2E (-1.4426950408889634f)

// ---------------------------------------------------------------------------
// Kernel 1: split-K(4) GEMM partials + fused x->out copy.
// grid (16 m, 8 n, 4 z) = 512 blocks, 128 thr, tile 64m x 64n.
// Micro-tile 8 cols (4 packed PAIRS) x 4 rows. W stored NATURALLY (LDS.64 =
// 2 consecutive cols); x stored duplicated (broadcast reads). Per warp per
// kk: W 512B + x ~128B smem traffic (vs 2KB+ before). Bias in z==0.
// ---------------------------------------------------------------------------
__global__ __launch_bounds__(128)
void gemm_kernel(const float* __restrict__ x, const float* __restrict__ W,
                 const float* __restrict__ b, float* __restrict__ out) {
    __shared__ __align__(16) float Xs[2][BK][132];  // dup rows: [kk][2r],[2r+1]
    __shared__ __align__(16) float Ws[2][BK][72];   // natural cols

    const int bm = blockIdx.x * 64;       // feat col tile
    const int bn = blockIdx.y * 64;       // row tile
    const int kz = blockIdx.z * 128;      // k quarter
    const int tid = threadIdx.x;
    const int cx = tid & 7;               // col-pair base
    const int ry = tid >> 3;              // 0..15 row base

    // fused x -> out copy (512 blocks x 128 thr = 65536 float4 = all of x)
    {
        int bid = blockIdx.x + blockIdx.y * 16 + blockIdx.z * 128;
        int idx = bid * 128 + tid;
        ((float4*)out)[(idx >> 7) * 144 + (idx & 127)] = ((const float4*)x)[idx];
    }

    ull acc[4][4];   // [r][c] = cols (2(cx+8c), +1) x row (ry+16r)
#pragma unroll
    for (int r = 0; r < 4; r++)
#pragma unroll
        for (int c = 0; c < 4; c++) acc[r][c] = 0ULL;

    float4 xs4[2], ws4[2];

#define GLOAD(step) do {                                                     \
    _Pragma("unroll")                                                        \
    for (int j = 0; j < 2; j++) {                                            \
        int idx = tid + j * 128; int rw = idx >> 2, kq = idx & 3;            \
        xs4[j] = *(const float4*)&x[(bn + rw) * INSIZE + kz +                \
                                    (step) * BK + kq * 4];                   \
        ws4[j] = *(const float4*)&W[(bm + rw) * INSIZE + kz +                \
                                    (step) * BK + kq * 4];                   \
    }                                                                        \
} while (0)

#define SSTORE(bf) do {                                                      \
    _Pragma("unroll")                                                        \
    for (int j = 0; j < 2; j++) {                                            \
        int idx = tid + j * 128; int rw = idx >> 2, kq = idx & 3;            \
        float xv[4] = {xs4[j].x, xs4[j].y, xs4[j].z, xs4[j].w};              \
        float wv[4] = {ws4[j].x, ws4[j].y, ws4[j].z, ws4[j].w};              \
        _Pragma("unroll")                                                    \
        for (int jj = 0; jj < 4; jj++) {                                     \
            *(float2*)&Xs[bf][kq * 4 + jj][2 * rw] =                         \
                make_float2(xv[jj], xv[jj]);                                 \
            Ws[bf][kq * 4 + jj][rw] = wv[jj];                                \
        }                                                                    \
    }                                                                        \
} while (0)

    GLOAD(0); SSTORE(0); __syncthreads();
    int buf = 0;

    for (int step = 1; step <= 8; step++) {
        const bool more = (step < 8);
        if (more) GLOAD(step);

#pragma unroll
        for (int kk = 0; kk < BK; kk++) {
            ull xr[4], wp[4];
#pragma unroll
            for (int r = 0; r < 4; r++)
                xr[r] = *(const ull*)&Xs[buf][kk][2 * (ry + 16 * r)];
#pragma unroll
            for (int c = 0; c < 4; c++)
                wp[c] = *(const ull*)&Ws[buf][kk][2 * (cx + 8 * c)];
#pragma unroll
            for (int r = 0; r < 4; r++)
#pragma unroll
                for (int c = 0; c < 4; c++)
                    acc[r][c] = fmaf32x2(wp[c], xr[r], acc[r][c]);
        }

        if (more) { buf ^= 1; SSTORE(buf); __syncthreads(); }
    }
#undef GLOAD
#undef SSTORE

    // epilogue: K-major partial store, bias folded into z==0
    float* dstz = g_P + blockIdx.z * PART;
#pragma unroll
    for (int c = 0; c < 4; c++) {
        const int col0 = 2 * cx + 16 * c;           // within 64-col tile
        ull bb = 0ULL;
        if (blockIdx.z == 0) bb = *(const ull*)&b[bm + col0];
        float* dbase = dstz + (bm / 16 + c) * (NROWS * DD) + (col0 & 15);
#pragma unroll
        for (int r = 0; r < 4; r++) {
            const int row = bn + ry + 16 * r;
            ull v = addf32x2(acc[r][c], bb);
            *(float2*)&dbase[row * DD] = make_float2(lo32(v), hi32(v));
        }
    }
}

// ---------------------------------------------------------------------------
// Kernel 2: symmetric pairwise + inline finalize.
// grid (36 units, 16 kgroups), 256 thr. Stripes assembled from the 4 g_P
// partials via register prefetch (no sumfeat kernel). After all 36 units of
// a kgroup finish (fence + atomic ticket), the last block writes o_b for its
// 4 k's (deterministic values; only the executor varies).
// ---------------------------------------------------------------------------
__global__ __launch_bounds__(256)
void pairwise_kernel(float* __restrict__ out) {
    __shared__ __align__(16) ull sFA[T * 8];        // +tile a (4 KB)
    __shared__ __align__(16) ull sFB[T * 8];        // +tile b (4 KB)
    __shared__ float sE[2 * T * 32];                // 16 KB
    __shared__ float sTot[8][32];
    __shared__ int sT;

    const int u  = blockIdx.x;
    const int kg = blockIdx.y;
    const int a  = c_ua[u];
    const int bt = c_ub[u];
    const bool diag = (a == bt);

    const int tid = threadIdx.x;
    const int lane = tid & 31, w = tid >> 5;
    const int h = w >> 2, s = w & 3;
    const int iL = h * 32 + lane;
    const int jb = s * 16;

    float4 pa0, pa1, pa2, pa3, pb0, pb1, pb2, pb3;

#define PLOAD(t) do {                                                        \
    const int _k = kg * 4 + (t);                                             \
    const float* _pa = g_P + _k * 8192 + a * 1024 + tid * 4;                 \
    pa0 = *(const float4*)_pa;                                               \
    pa1 = *(const float4*)(_pa + PART);                                      \
    pa2 = *(const float4*)(_pa + 2 * PART);                                  \
    pa3 = *(const float4*)(_pa + 3 * PART);                                  \
    if (!diag) {                                                             \
        const float* _pb = g_P + _k * 8192 + bt * 1024 + tid * 4;            \
        pb0 = *(const float4*)_pb;                                           \
        pb1 = *(const float4*)(_pb + PART);                                  \
        pb2 = *(const float4*)(_pb + 2 * PART);                              \
        pb3 = *(const float4*)(_pb + 3 * PART);                              \
    }                                                                        \
} while (0)

    PLOAD(0);

    const ull SGN = 0x8000000080000000ULL;
    const ull ABSM = 0x7fffffff7fffffffULL;

    for (int t = 0; t < 4; t++) {
        // assemble slabs from prefetched partials
        {
            float4 sa;
            sa.x = (pa0.x + pa1.x) + (pa2.x + pa3.x);
            sa.y = (pa0.y + pa1.y) + (pa2.y + pa3.y);
            sa.z = (pa0.z + pa1.z) + (pa2.z + pa3.z);
            sa.w = (pa0.w + pa1.w) + (pa2.w + pa3.w);
            ((float4*)sFA)[tid] = sa;
            if (!diag) {
                float4 sb;
                sb.x = (pb0.x + pb1.x) + (pb2.x + pb3.x);
                sb.y = (pb0.y + pb1.y) + (pb2.y + pb3.y);
                sb.z = (pb0.z + pb1.z) + (pb2.z + pb3.z);
                sb.w = (pb0.w + pb1.w) + (pb2.w + pb3.w);
                ((float4*)sFB)[tid] = sb;
            }
        }
        __syncthreads();
        if (t < 3) PLOAD(t + 1);   // LDGs overlap compute

        const ull* slabA = sFA;
        const ull* slabB = diag ? sFA : sFB;

        ull fi[8];
        {
            const ulonglong2* p = (const ulonglong2*)&slabA[iL * 8];
            ulonglong2 f0 = p[0], f1 = p[1], f2 = p[2], f3 = p[3];
            fi[0] = f0.x ^ SGN; fi[1] = f0.y ^ SGN;
            fi[2] = f1.x ^ SGN; fi[3] = f1.y ^ SGN;
            fi[4] = f2.x ^ SGN; fi[5] = f2.y ^ SGN;
            fi[6] = f3.x ^ SGN; fi[7] = f3.y ^ SGN;
        }

        float ti = 0.f;
#pragma unroll 4
        for (int jj = 0; jj < 16; jj++) {
            const int j = jb + jj;
            const ulonglong2* row = (const ulonglong2*)&slabB[j * 8];
            ulonglong2 q0 = row[0], q1 = row[1], q2 = row[2], q3 = row[3];
            ull d0 = addf32x2(fi[0], q0.x) & ABSM;
            ull d1 = addf32x2(fi[1], q0.y) & ABSM;
            ull d2 = addf32x2(fi[2], q1.x) & ABSM;
            ull d3 = addf32x2(fi[3], q1.y) & ABSM;
            ull d4 = addf32x2(fi[4], q2.x) & ABSM;
            ull d5 = addf32x2(fi[5], q2.y) & ABSM;
            ull d6 = addf32x2(fi[6], q3.x) & ABSM;
            ull d7 = addf32x2(fi[7], q3.y) & ABSM;
            ull sm = addf32x2(addf32x2(addf32x2(d0, d1), addf32x2(d2, d3)),
                              addf32x2(addf32x2(d4, d5), addf32x2(d6, d7)));
            float e = ex2f((lo32(sm) + hi32(sm)) * NLOG2E);
            ti += e;
            if (!diag) sE[h * (T * 32) + j * 32 + lane] = e;
        }
        sTot[w][lane] = ti;
        __syncthreads();

        const int k = kg * 4 + t;
        if (!diag) {
#pragma unroll
            for (int jj = 0; jj < 8; jj++) {
                const int j = w * 8 + jj;
                float v = sE[j * 32 + lane] + sE[T * 32 + j * 32 + lane];
                v += __shfl_xor_sync(0xffffffffu, v, 16);
                v += __shfl_xor_sync(0xffffffffu, v, 8);
                v += __shfl_xor_sync(0xffffffffu, v, 4);
                v += __shfl_xor_sync(0xffffffffu, v, 2);
                v += __shfl_xor_sync(0xffffffffu, v, 1);
                if (lane == 0)
                    g_part[(k * NROWS + bt * T + j) * 8 + a] = v;
            }
        }
        if (tid < 64) {
            const int hh = tid >> 5, l = tid & 31;
            float tt = sTot[hh * 4 + 0][l] + sTot[hh * 4 + 1][l] +
                       sTot[hh * 4 + 2][l] + sTot[hh * 4 + 3][l];
            g_part[(k * NROWS + a * T + tid) * 8 + bt] = tt;
        }
        __syncthreads();   // protect sE/sTot/sF reuse next t
    }
#undef PLOAD

    // ---- inline finalize: last of the 36 units of this kgroup ----
    __threadfence();
    if (tid == 0) sT = atomicAdd(&g_cnt[kg], 1);
    __syncthreads();
    if (sT == 35) {
#pragma unroll
        for (int jj = 0; jj < 8; jj++) {
            const int o = jj * 256 + tid;          // 0..2047
            const int i = o & 511;
            const int kl = o >> 9;
            const float4* p =
                (const float4*)&g_part[((kg * 4 + kl) * NROWS + i) * 8];
            float4 u0 = p[0], u1 = p[1];
            float tt = (u0.x + u0.y) + (u0.z + u0.w) +
                       (u1.x + u1.y) + (u1.z + u1.w) - 1.0f;
            out[i * OUTW + INSIZE + kg * 4 + kl] = tt;
        }
        __syncthreads();
        if (tid == 0) g_cnt[kg] = 0;   // reset for next graph replay
    }
}

// ---------------------------------------------------------------------------
extern "C" void kernel_launch(void* const* d_in, const int* in_sizes, int n_in,
                              void* d_out, int out_size) {
    const float* x = (const float*)d_in[0];   // [512,512]
    const float* W = (const float*)d_in[1];   // [1024,512]
    const float* b = (const float*)d_in[2];   // [1024]
    float* out = (float*)d_out;               // [512,576]

    gemm_kernel<<<dim3(16, 8, 4), 128>>>(x, W, b, out);
    pairwise_kernel<<<dim3(36, 16), 256>>>(out);
}

// round 14
// speedup vs baseline: 1.1016x; 1.1016x over previous
#include <cuda_runtime.h>
#include <cstdint>

#define NROWS  512
#define INSIZE 512
#define KK     64
#define DD     16
#define MM     (KK * DD)        // 1024
#define OUTW   (INSIZE + KK)    // 576
#define BK     16
#define T      64
#define PART   (NROWS * MM)     // one split-K partial, K-major [k][row][d]

typedef unsigned long long ull;

__device__ float g_P[4 * PART];          // split-K partials, K-major  8 MB
__device__ float g_feat[NROWS * MM];     // k-major feat (+bias)       2 MB
__device__ float g_part[NROWS * KK * 8]; // [k][i][slot]               1 MB
__device__ int   g_cnt[16];              // per-kgroup arrival counters

// 36 tile-units: 8 diagonal + 28 upper-triangle
__constant__ int c_ua[36] = {0,1,2,3,4,5,6,7, 0,0,0,0,0,0,0, 1,1,1,1,1,1,
                             2,2,2,2,2, 3,3,3,3, 4,4,4, 5,5, 6};
__constant__ int c_ub[36] = {0,1,2,3,4,5,6,7, 1,2,3,4,5,6,7, 2,3,4,5,6,7,
                             3,4,5,6,7, 4,5,6,7, 5,6,7, 6,7, 7};

// ---------------------------------------------------------------------------
// helpers
// ---------------------------------------------------------------------------
__device__ __forceinline__ ull addf32x2(ull a, ull b) {
    ull r;
    asm("add.rn.f32x2 %0, %1, %2;" : "=l"(r) : "l"(a), "l"(b));
    return r;
}
__device__ __forceinline__ ull fmaf32x2(ull a, ull b, ull c) {
    ull r;
    asm("fma.rn.f32x2 %0, %1, %2, %3;" : "=l"(r) : "l"(a), "l"(b), "l"(c));
    return r;
}
__device__ __forceinline__ float lo32(ull v) {
    return __uint_as_float((unsigned int)v);
}
__device__ __forceinline__ float hi32(ull v) {
    return __uint_as_float((unsigned int)(v >> 32));
}
__device__ __forceinline__ float ex2f(float v) {
    float r;
    asm("ex2.approx.f32 %0, %1;" : "=f"(r) : "f"(v));
    return r;
}
__device__ __forceinline__ unsigned su32(const void* p) {
    return (unsigned)__cvta_generic_to_shared(p);
}
#define CPA16(dst, src) \
    asm volatile("cp.async.cg.shared.global [%0], [%1], 16;" :: "r"(dst), "l"(src))
#define CPA_COMMIT() asm volatile("cp.async.commit_group;")
#define CPA_WAIT0()  asm volatile("cp.async.wait_group 0;")

#define NLOG2E (-1.4426950408889634f)

// ---------------------------------------------------------------------------
// Kernel 1: split-K(4) GEMM partials, 8x8 micro-tile. (R12 exact)
// ---------------------------------------------------------------------------
__global__ __launch_bounds__(128)
void gemm_kernel(const float* __restrict__ x, const float* __restrict__ W) {
    __shared__ __align__(16) float Xs[2][BK][68];   // transposed x, padded
    __shared__ __align__(16) ull   Wd[2][BK][129];  // dup W cols, padded

    const int bm = blockIdx.x * 128;
    const int bn = blockIdx.y * 64;
    const int kz = blockIdx.z * 128;
    const int tid = threadIdx.x;
    const int tx = tid & 15, ty = tid >> 4;

    ull acc[4][8];
#pragma unroll
    for (int rp = 0; rp < 4; rp++)
#pragma unroll
        for (int c = 0; c < 8; c++) acc[rp][c] = 0ULL;

    float4 xs4[2], ws4[4];

#define GLOAD(step) do {                                                     \
    _Pragma("unroll")                                                        \
    for (int j = 0; j < 2; j++) {                                            \
        int idx = tid + j * 128; int row = idx >> 2, kq = idx & 3;           \
        xs4[j] = *(const float4*)&x[(bn + row) * INSIZE + kz +               \
                                    (step) * BK + kq * 4];                   \
    }                                                                        \
    _Pragma("unroll")                                                        \
    for (int j = 0; j < 4; j++) {                                            \
        int idx = tid + j * 128; int col = idx >> 2, kq = idx & 3;           \
        ws4[j] = *(const float4*)&W[(bm + col) * INSIZE + kz +               \
                                    (step) * BK + kq * 4];                   \
    }                                                                        \
} while (0)

#define SSTORE(bf) do {                                                      \
    _Pragma("unroll")                                                        \
    for (int j = 0; j < 2; j++) {                                            \
        int idx = tid + j * 128; int row = idx >> 2, kq = idx & 3;           \
        float v[4] = {xs4[j].x, xs4[j].y, xs4[j].z, xs4[j].w};               \
        _Pragma("unroll")                                                    \
        for (int jj = 0; jj < 4; jj++) Xs[bf][kq * 4 + jj][row] = v[jj];     \
    }                                                                        \
    _Pragma("unroll")                                                        \
    for (int j = 0; j < 4; j++) {                                            \
        int idx = tid + j * 128; int col = idx >> 2, kq = idx & 3;           \
        float v[4] = {ws4[j].x, ws4[j].y, ws4[j].z, ws4[j].w};               \
        _Pragma("unroll")                                                    \
        for (int jj = 0; jj < 4; jj++)                                       \
            *(float2*)&Wd[bf][kq * 4 + jj][col] = make_float2(v[jj], v[jj]); \
    }                                                                        \
} while (0)

    GLOAD(0); SSTORE(0); __syncthreads();
    int buf = 0;

    for (int step = 1; step <= 8; step++) {
        const bool more = (step < 8);
        if (more) GLOAD(step);

#pragma unroll
        for (int kk = 0; kk < BK; kk++) {
            ulonglong2 xp0 = *(const ulonglong2*)&Xs[buf][kk][8 * ty];
            ulonglong2 xp1 = *(const ulonglong2*)&Xs[buf][kk][8 * ty + 4];
            ull xr[4] = {xp0.x, xp0.y, xp1.x, xp1.y};
            ull wd[8];
#pragma unroll
            for (int c = 0; c < 8; c++) wd[c] = Wd[buf][kk][tx + 16 * c];
#pragma unroll
            for (int rp = 0; rp < 4; rp++)
#pragma unroll
                for (int c = 0; c < 8; c++)
                    acc[rp][c] = fmaf32x2(wd[c], xr[rp], acc[rp][c]);
        }

        if (more) { buf ^= 1; SSTORE(buf); __syncthreads(); }
    }
#undef GLOAD
#undef SSTORE

    float* dstz = g_P + blockIdx.z * PART;
#pragma unroll
    for (int c = 0; c < 8; c++) {
        float* d = dstz + (bm / 16 + c) * (NROWS * DD) + tx;
#pragma unroll
        for (int rp = 0; rp < 4; rp++) {
            const int r0 = bn + 8 * ty + 2 * rp;
            d[r0 * DD]       = lo32(acc[rp][c]);
            d[(r0 + 1) * DD] = hi32(acc[rp][c]);
        }
    }
}

// ---------------------------------------------------------------------------
// Kernel 2: g_feat = sum of 4 partials + bias; fused x -> out copy. (R12)
// ---------------------------------------------------------------------------
__global__ __launch_bounds__(256)
void sumfeat_kernel(const float* __restrict__ b, const float* __restrict__ x,
                    float* __restrict__ out) {
    const int idx = blockIdx.x * 256 + threadIdx.x;
    const int kg = idx >> 11;
    const int q = idx & 3;
    float4 v0 = ((const float4*)g_P)[idx];
    float4 v1 = ((const float4*)(g_P + PART))[idx];
    float4 v2 = ((const float4*)(g_P + 2 * PART))[idx];
    float4 v3 = ((const float4*)(g_P + 3 * PART))[idx];
    float4 bb = *(const float4*)&b[kg * DD + q * 4];
    float4 o;
    o.x = v0.x + v1.x + v2.x + v3.x + bb.x;
    o.y = v0.y + v1.y + v2.y + v3.y + bb.y;
    o.z = v0.z + v1.z + v2.z + v3.z + bb.z;
    o.w = v0.w + v1.w + v2.w + v3.w + bb.w;
    ((float4*)g_feat)[idx] = o;

    if (idx < NROWS * 128) {    // 65536 float4 = all of x
        ((float4*)out)[(idx >> 7) * 144 + (idx & 127)] = ((const float4*)x)[idx];
    }
}

// ---------------------------------------------------------------------------
// Kernel 3: symmetric pairwise (R12 body, cp.async stripes) + inline
// ticket-finalize (validated in R13). Last of the 36 units per kgroup writes
// o_b for its 4 k's; values deterministic (fixed slot order).
// ---------------------------------------------------------------------------
__global__ __launch_bounds__(256)
void pairwise_kernel(float* __restrict__ out) {
    __shared__ __align__(16) ull sF[2][2][T * 8];
    __shared__ float sE[2 * T * 32];
    __shared__ float sTot[8][32];
    __shared__ int sT;

    const int u  = blockIdx.x;
    const int kg = blockIdx.y;
    const int a  = c_ua[u];
    const int bt = c_ub[u];
    const bool diag = (a == bt);

    const int tid = threadIdx.x;
    const int lane = tid & 31, w = tid >> 5;
    const int h = w >> 2, s = w & 3;
    const int iL = h * 32 + lane;
    const int jb = s * 16;

#define ISSUE(t) do {                                                        \
    const int _k = kg * 4 + (t);                                             \
    const int _bk = (t) & 1;                                                 \
    CPA16(su32((char*)&sF[_bk][0][0] + tid * 16),                            \
          g_feat + _k * 8192 + a * 1024 + tid * 4);                          \
    if (!diag)                                                               \
        CPA16(su32((char*)&sF[_bk][1][0] + tid * 16),                        \
              g_feat + _k * 8192 + bt * 1024 + tid * 4);                     \
} while (0)

    ISSUE(0); CPA_COMMIT();

    const ull SGN = 0x8000000080000000ULL;
    const ull ABSM = 0x7fffffff7fffffffULL;

    for (int t = 0; t < 4; t++) {
        CPA_WAIT0();
        __syncthreads();
        if (t < 3) { ISSUE(t + 1); CPA_COMMIT(); }

        const int bank = t & 1;
        const ull* slabA = sF[bank][0];
        const ull* slabB = diag ? sF[bank][0] : sF[bank][1];

        ull fi[8];
        {
            const ulonglong2* p = (const ulonglong2*)&slabA[iL * 8];
            ulonglong2 f0 = p[0], f1 = p[1], f2 = p[2], f3 = p[3];
            fi[0] = f0.x ^ SGN; fi[1] = f0.y ^ SGN;
            fi[2] = f1.x ^ SGN; fi[3] = f1.y ^ SGN;
            fi[4] = f2.x ^ SGN; fi[5] = f2.y ^ SGN;
            fi[6] = f3.x ^ SGN; fi[7] = f3.y ^ SGN;
        }

        float ti = 0.f;
#pragma unroll 4
        for (int jj = 0; jj < 16; jj++) {
            const int j = jb + jj;
            const ulonglong2* row = (const ulonglong2*)&slabB[j * 8];
            ulonglong2 q0 = row[0], q1 = row[1], q2 = row[2], q3 = row[3];
            ull d0 = addf32x2(fi[0], q0.x) & ABSM;
            ull d1 = addf32x2(fi[1], q0.y) & ABSM;
            ull d2 = addf32x2(fi[2], q1.x) & ABSM;
            ull d3 = addf32x2(fi[3], q1.y) & ABSM;
            ull d4 = addf32x2(fi[4], q2.x) & ABSM;
            ull d5 = addf32x2(fi[5], q2.y) & ABSM;
            ull d6 = addf32x2(fi[6], q3.x) & ABSM;
            ull d7 = addf32x2(fi[7], q3.y) & ABSM;
            ull sm = addf32x2(addf32x2(addf32x2(d0, d1), addf32x2(d2, d3)),
                              addf32x2(addf32x2(d4, d5), addf32x2(d6, d7)));
            float e = ex2f((lo32(sm) + hi32(sm)) * NLOG2E);
            ti += e;
            if (!diag) sE[h * (T * 32) + j * 32 + lane] = e;
        }
        sTot[w][lane] = ti;
        __syncthreads();

        const int k = kg * 4 + t;
        if (!diag) {
#pragma unroll
            for (int jj = 0; jj < 8; jj++) {
                const int j = w * 8 + jj;
                float v = sE[j * 32 + lane] + sE[T * 32 + j * 32 + lane];
                v += __shfl_xor_sync(0xffffffffu, v, 16);
                v += __shfl_xor_sync(0xffffffffu, v, 8);
                v += __shfl_xor_sync(0xffffffffu, v, 4);
                v += __shfl_xor_sync(0xffffffffu, v, 2);
                v += __shfl_xor_sync(0xffffffffu, v, 1);
                if (lane == 0)
                    g_part[(k * NROWS + bt * T + j) * 8 + a] = v;
            }
        }
        if (tid < 64) {
            const int hh = tid >> 5, l = tid & 31;
            float tt = sTot[hh * 4 + 0][l] + sTot[hh * 4 + 1][l] +
                       sTot[hh * 4 + 2][l] + sTot[hh * 4 + 3][l];
            g_part[(k * NROWS + a * T + tid) * 8 + bt] = tt;
        }
    }
#undef ISSUE

    // ---- inline finalize: last of the 36 units of this kgroup ----
    __threadfence();
    if (tid == 0) sT = atomicAdd(&g_cnt[kg], 1);
    __syncthreads();
    if (sT == 35) {
#pragma unroll
        for (int jj = 0; jj < 8; jj++) {
            const int o = jj * 256 + tid;          // 0..2047
            const int i = o & 511;
            const int kl = o >> 9;
            const float4* p =
                (const float4*)&g_part[((kg * 4 + kl) * NROWS + i) * 8];
            float4 u0 = p[0], u1 = p[1];
            float tt = (u0.x + u0.y) + (u0.z + u0.w) +
                       (u1.x + u1.y) + (u1.z + u1.w) - 1.0f;
            out[i * OUTW + INSIZE + kg * 4 + kl] = tt;
        }
        __syncthreads();
        if (tid == 0) g_cnt[kg] = 0;   // reset for next graph replay
    }
}

// ---------------------------------------------------------------------------
extern "C" void kernel_launch(void* const* d_in, const int* in_sizes, int n_in,
                              void* d_out, int out_size) {
    const float* x = (const float*)d_in[0];   // [512,512]
    const float* W = (const float*)d_in[1];   // [1024,512]
    const float* b = (const float*)d_in[2];   // [1024]
    float* out = (float*)d_out;               // [512,576]

    gemm_kernel<<<dim3(8, 8, 4), 128>>>(x, W);
    sumfeat_kernel<<<512, 256>>>(b, x, out);
    pairwise_kernel<<<dim3(36, 16), 256>>>(out);
}

// round 15
// speedup vs baseline: 1.2824x; 1.1641x over previous
#include <cuda_runtime.h>
#include <cstdint>

#define NROWS  512
#define INSIZE 512
#define KK     64
#define DD     16
#define MM     (KK * DD)        // 1024
#define OUTW   (INSIZE + KK)    // 576
#define BK     16
#define T      64
#define PART   (NROWS * MM)     // one split-K partial, K-major [k][row][d]
#define NSPLIT 8

typedef unsigned long long ull;

__device__ float g_P[NSPLIT * PART];     // split-K partials, K-major  16 MB
__device__ float g_feat[NROWS * MM];     // k-major feat (+bias)       2 MB
__device__ float g_part[NROWS * KK * 8]; // [k][i][slot]               1 MB

// 36 tile-units: 8 diagonal + 28 upper-triangle
__constant__ int c_ua[36] = {0,1,2,3,4,5,6,7, 0,0,0,0,0,0,0, 1,1,1,1,1,1,
                             2,2,2,2,2, 3,3,3,3, 4,4,4, 5,5, 6};
__constant__ int c_ub[36] = {0,1,2,3,4,5,6,7, 1,2,3,4,5,6,7, 2,3,4,5,6,7,
                             3,4,5,6,7, 4,5,6,7, 5,6,7, 6,7, 7};

// ---------------------------------------------------------------------------
// helpers
// ---------------------------------------------------------------------------
__device__ __forceinline__ ull addf32x2(ull a, ull b) {
    ull r;
    asm("add.rn.f32x2 %0, %1, %2;" : "=l"(r) : "l"(a), "l"(b));
    return r;
}
__device__ __forceinline__ ull fmaf32x2(ull a, ull b, ull c) {
    ull r;
    asm("fma.rn.f32x2 %0, %1, %2, %3;" : "=l"(r) : "l"(a), "l"(b), "l"(c));
    return r;
}
__device__ __forceinline__ float lo32(ull v) {
    return __uint_as_float((unsigned int)v);
}
__device__ __forceinline__ float hi32(ull v) {
    return __uint_as_float((unsigned int)(v >> 32));
}
__device__ __forceinline__ float ex2f(float v) {
    float r;
    asm("ex2.approx.f32 %0, %1;" : "=f"(r) : "f"(v));
    return r;
}
__device__ __forceinline__ unsigned su32(const void* p) {
    return (unsigned)__cvta_generic_to_shared(p);
}
#define CPA16(dst, src) \
    asm volatile("cp.async.cg.shared.global [%0], [%1], 16;" :: "r"(dst), "l"(src))
#define CPA_COMMIT() asm volatile("cp.async.commit_group;")
#define CPA_WAIT0()  asm volatile("cp.async.wait_group 0;")

#define NLOG2E (-1.4426950408889634f)

// ---------------------------------------------------------------------------
// Kernel 1: split-K(8) GEMM partials, 8x8 micro-tile.
// grid (8 m, 8 n, 8 z) = 512 blocks, 128 thr, tile 128m x 64n, k=64/block.
// Inner stream identical to R12; only the k-split depth changed (occupancy).
// ---------------------------------------------------------------------------
__global__ __launch_bounds__(128)
void gemm_kernel(const float* __restrict__ x, const float* __restrict__ W) {
    __shared__ __align__(16) float Xs[2][BK][68];   // transposed x, padded
    __shared__ __align__(16) ull   Wd[2][BK][129];  // dup W cols, padded

    const int bm = blockIdx.x * 128;
    const int bn = blockIdx.y * 64;
    const int kz = blockIdx.z * 64;
    const int tid = threadIdx.x;
    const int tx = tid & 15, ty = tid >> 4;

    ull acc[4][8];
#pragma unroll
    for (int rp = 0; rp < 4; rp++)
#pragma unroll
        for (int c = 0; c < 8; c++) acc[rp][c] = 0ULL;

    float4 xs4[2], ws4[4];

#define GLOAD(step) do {                                                     \
    _Pragma("unroll")                                                        \
    for (int j = 0; j < 2; j++) {                                            \
        int idx = tid + j * 128; int row = idx >> 2, kq = idx & 3;           \
        xs4[j] = *(const float4*)&x[(bn + row) * INSIZE + kz +               \
                                    (step) * BK + kq * 4];                   \
    }                                                                        \
    _Pragma("unroll")                                                        \
    for (int j = 0; j < 4; j++) {                                            \
        int idx = tid + j * 128; int col = idx >> 2, kq = idx & 3;           \
        ws4[j] = *(const float4*)&W[(bm + col) * INSIZE + kz +               \
                                    (step) * BK + kq * 4];                   \
    }                                                                        \
} while (0)

#define SSTORE(bf) do {                                                      \
    _Pragma("unroll")                                                        \
    for (int j = 0; j < 2; j++) {                                            \
        int idx = tid + j * 128; int row = idx >> 2, kq = idx & 3;           \
        float v[4] = {xs4[j].x, xs4[j].y, xs4[j].z, xs4[j].w};               \
        _Pragma("unroll")                                                    \
        for (int jj = 0; jj < 4; jj++) Xs[bf][kq * 4 + jj][row] = v[jj];     \
    }                                                                        \
    _Pragma("unroll")                                                        \
    for (int j = 0; j < 4; j++) {                                            \
        int idx = tid + j * 128; int col = idx >> 2, kq = idx & 3;           \
        float v[4] = {ws4[j].x, ws4[j].y, ws4[j].z, ws4[j].w};               \
        _Pragma("unroll")                                                    \
        for (int jj = 0; jj < 4; jj++)                                       \
            *(float2*)&Wd[bf][kq * 4 + jj][col] = make_float2(v[jj], v[jj]); \
    }                                                                        \
} while (0)

    GLOAD(0); SSTORE(0); __syncthreads();
    int buf = 0;

    for (int step = 1; step <= 4; step++) {
        const bool more = (step < 4);
        if (more) GLOAD(step);

#pragma unroll
        for (int kk = 0; kk < BK; kk++) {
            ulonglong2 xp0 = *(const ulonglong2*)&Xs[buf][kk][8 * ty];
            ulonglong2 xp1 = *(const ulonglong2*)&Xs[buf][kk][8 * ty + 4];
            ull xr[4] = {xp0.x, xp0.y, xp1.x, xp1.y};
            ull wd[8];
#pragma unroll
            for (int c = 0; c < 8; c++) wd[c] = Wd[buf][kk][tx + 16 * c];
#pragma unroll
            for (int rp = 0; rp < 4; rp++)
#pragma unroll
                for (int c = 0; c < 8; c++)
                    acc[rp][c] = fmaf32x2(wd[c], xr[rp], acc[rp][c]);
        }

        if (more) { buf ^= 1; SSTORE(buf); __syncthreads(); }
    }
#undef GLOAD
#undef SSTORE

    float* dstz = g_P + blockIdx.z * PART;
#pragma unroll
    for (int c = 0; c < 8; c++) {
        float* d = dstz + (bm / 16 + c) * (NROWS * DD) + tx;
#pragma unroll
        for (int rp = 0; rp < 4; rp++) {
            const int r0 = bn + 8 * ty + 2 * rp;
            d[r0 * DD]       = lo32(acc[rp][c]);
            d[(r0 + 1) * DD] = hi32(acc[rp][c]);
        }
    }
}

// ---------------------------------------------------------------------------
// Kernel 2: g_feat = sum of 8 partials + bias; fused x -> out copy.
// ---------------------------------------------------------------------------
__global__ __launch_bounds__(256)
void sumfeat_kernel(const float* __restrict__ b, const float* __restrict__ x,
                    float* __restrict__ out) {
    const int idx = blockIdx.x * 256 + threadIdx.x;
    const int kg = idx >> 11;
    const int q = idx & 3;
    float4 acc = make_float4(0.f, 0.f, 0.f, 0.f);
#pragma unroll
    for (int p = 0; p < NSPLIT; p++) {
        float4 v = ((const float4*)(g_P + p * PART))[idx];
        acc.x += v.x; acc.y += v.y; acc.z += v.z; acc.w += v.w;
    }
    float4 bb = *(const float4*)&b[kg * DD + q * 4];
    acc.x += bb.x; acc.y += bb.y; acc.z += bb.z; acc.w += bb.w;
    ((float4*)g_feat)[idx] = acc;

    if (idx < NROWS * 128) {    // 65536 float4 = all of x
        ((float4*)out)[(idx >> 7) * 144 + (idx & 127)] = ((const float4*)x)[idx];
    }
}

// ---------------------------------------------------------------------------
// Kernel 3: symmetric pairwise, k-grouped, cp.async stripes. (R12 exact)
// ---------------------------------------------------------------------------
__global__ __launch_bounds__(256)
void pairwise_kernel() {
    __shared__ __align__(16) ull sF[2][2][T * 8];
    __shared__ float sE[2 * T * 32];
    __shared__ float sTot[8][32];

    const int u  = blockIdx.x;
    const int kg = blockIdx.y;
    const int a  = c_ua[u];
    const int bt = c_ub[u];
    const bool diag = (a == bt);

    const int tid = threadIdx.x;
    const int lane = tid & 31, w = tid >> 5;
    const int h = w >> 2, s = w & 3;
    const int iL = h * 32 + lane;
    const int jb = s * 16;

#define ISSUE(t) do {                                                        \
    const int _k = kg * 4 + (t);                                             \
    const int _bk = (t) & 1;                                                 \
    CPA16(su32((char*)&sF[_bk][0][0] + tid * 16),                            \
          g_feat + _k * 8192 + a * 1024 + tid * 4);                          \
    if (!diag)                                                               \
        CPA16(su32((char*)&sF[_bk][1][0] + tid * 16),                        \
              g_feat + _k * 8192 + bt * 1024 + tid * 4);                     \
} while (0)

    ISSUE(0); CPA_COMMIT();

    const ull SGN = 0x8000000080000000ULL;
    const ull ABSM = 0x7fffffff7fffffffULL;

    for (int t = 0; t < 4; t++) {
        CPA_WAIT0();
        __syncthreads();
        if (t < 3) { ISSUE(t + 1); CPA_COMMIT(); }

        const int bank = t & 1;
        const ull* slabA = sF[bank][0];
        const ull* slabB = diag ? sF[bank][0] : sF[bank][1];

        ull fi[8];
        {
            const ulonglong2* p = (const ulonglong2*)&slabA[iL * 8];
            ulonglong2 f0 = p[0], f1 = p[1], f2 = p[2], f3 = p[3];
            fi[0] = f0.x ^ SGN; fi[1] = f0.y ^ SGN;
            fi[2] = f1.x ^ SGN; fi[3] = f1.y ^ SGN;
            fi[4] = f2.x ^ SGN; fi[5] = f2.y ^ SGN;
            fi[6] = f3.x ^ SGN; fi[7] = f3.y ^ SGN;
        }

        float ti = 0.f;
#pragma unroll 4
        for (int jj = 0; jj < 16; jj++) {
            const int j = jb + jj;
            const ulonglong2* row = (const ulonglong2*)&slabB[j * 8];
            ulonglong2 q0 = row[0], q1 = row[1], q2 = row[2], q3 = row[3];
            ull d0 = addf32x2(fi[0], q0.x) & ABSM;
            ull d1 = addf32x2(fi[1], q0.y) & ABSM;
            ull d2 = addf32x2(fi[2], q1.x) & ABSM;
            ull d3 = addf32x2(fi[3], q1.y) & ABSM;
            ull d4 = addf32x2(fi[4], q2.x) & ABSM;
            ull d5 = addf32x2(fi[5], q2.y) & ABSM;
            ull d6 = addf32x2(fi[6], q3.x) & ABSM;
            ull d7 = addf32x2(fi[7], q3.y) & ABSM;
            ull sm = addf32x2(addf32x2(addf32x2(d0, d1), addf32x2(d2, d3)),
                              addf32x2(addf32x2(d4, d5), addf32x2(d6, d7)));
            float e = ex2f((lo32(sm) + hi32(sm)) * NLOG2E);
            ti += e;
            if (!diag) sE[h * (T * 32) + j * 32 + lane] = e;
        }
        sTot[w][lane] = ti;
        __syncthreads();

        const int k = kg * 4 + t;
        if (!diag) {
#pragma unroll
            for (int jj = 0; jj < 8; jj++) {
                const int j = w * 8 + jj;
                float v = sE[j * 32 + lane] + sE[T * 32 + j * 32 + lane];
                v += __shfl_xor_sync(0xffffffffu, v, 16);
                v += __shfl_xor_sync(0xffffffffu, v, 8);
                v += __shfl_xor_sync(0xffffffffu, v, 4);
                v += __shfl_xor_sync(0xffffffffu, v, 2);
                v += __shfl_xor_sync(0xffffffffu, v, 1);
                if (lane == 0)
                    g_part[(k * NROWS + bt * T + j) * 8 + a] = v;
            }
        }
        if (tid < 64) {
            const int hh = tid >> 5, l = tid & 31;
            float tt = sTot[hh * 4 + 0][l] + sTot[hh * 4 + 1][l] +
                       sTot[hh * 4 + 2][l] + sTot[hh * 4 + 3][l];
            g_part[(k * NROWS + a * T + tid) * 8 + bt] = tt;
        }
    }
#undef ISSUE
}

// ---------------------------------------------------------------------------
// Kernel 4: finalize o_b only. (R12 exact)
// ---------------------------------------------------------------------------
__global__ __launch_bounds__(256)
void final_kernel(float* __restrict__ out) {
    __shared__ float s[64][9];      // [k][ii], padded
    const int i0 = blockIdx.x * 8;
    const int tid = threadIdx.x;

    const int ii = tid & 7, kq = tid >> 3;      // kq 0..31
#pragma unroll
    for (int it = 0; it < 2; it++) {
        const int k = it * 32 + kq;
        const float4* p = (const float4*)&g_part[(k * NROWS + i0 + ii) * 8];
        float4 u0 = p[0], u1 = p[1];
        s[k][ii] = (u0.x + u0.y) + (u0.z + u0.w) +
                   (u1.x + u1.y) + (u1.z + u1.w) - 1.0f;
    }
    __syncthreads();

    if (tid < 128) {
        const int ii2 = tid >> 4, q = tid & 15;
        float4 o;
        o.x = s[q * 4 + 0][ii2];
        o.y = s[q * 4 + 1][ii2];
        o.z = s[q * 4 + 2][ii2];
        o.w = s[q * 4 + 3][ii2];
        *(float4*)&out[(i0 + ii2) * OUTW + INSIZE + q * 4] = o;
    }
}

// ---------------------------------------------------------------------------
extern "C" void kernel_launch(void* const* d_in, const int* in_sizes, int n_in,
                              void* d_out, int out_size) {
    const float* x = (const float*)d_in[0];   // [512,512]
    const float* W = (const float*)d_in[1];   // [1024,512]
    const float* b = (const float*)d_in[2];   // [1024]
    float* out = (float*)d_out;               // [512,576]

    gemm_kernel<<<dim3(8, 8, 8), 128>>>(x, W);
    sumfeat_kernel<<<512, 256>>>(b, x, out);
    pairwise_kernel<<<dim3(36, 16), 256>>>();
    final_kernel<<<64, 256>>>(out);
}